// round 11
// baseline (speedup 1.0000x reference)
#include <cuda_runtime.h>
#include <cuda_bf16.h>
#include <math.h>
#include <stdint.h>

// Problem dims
#define TT    1024
#define HID   256
#define FIN   40
#define NSPK  1251
#define BATCH 64

// Global-fallback pipeline config
#define G      32
#define CHUNK  8
#define ROWS   32
#define NCTA   (3 * G)

// Cluster pipeline config
#define GC     16       // CTAs per layer-cluster
#define RR     64       // gate rows per CTA
#define CH     16       // h-indices per CTA
#define CW     64       // columns per dot warp
#define NW     8        // dot warps (warp 8 = reducer)
#define THR_CL 288

#define CANARY_I 0x7fb0beef

__device__ float g_hbuf[3][TT + 1][HID];
__device__ float g_xg0[TT][32][32];
__device__ float g_logits[TT * NSPK];

#define FMA2(d, a, b, c) \
    asm("fma.rn.f32x2 %0, %1, %2, %3;" : "=l"(d) : "l"(a), "l"(b), "l"(c))

__device__ __forceinline__ float tanh_fast(float x) {
    float r;
    asm("tanh.approx.f32 %0, %1;" : "=f"(r) : "f"(x));
    return r;
}
__device__ __forceinline__ float sig_fast(float x) {
    return 0.5f * tanh_fast(0.5f * x) + 0.5f;
}
__device__ __forceinline__ float poll_ld(const float* p) {
    float v;
    asm volatile("ld.volatile.global.f32 %0, [%1];" : "=f"(v) : "l"(p) : "memory");
    return v;
}
__device__ __forceinline__ void st_vol(float* p, float v) {
    asm volatile("st.volatile.global.f32 [%0], %1;" :: "l"(p), "f"(v) : "memory");
}
__device__ __forceinline__ float lds_vol(uint32_t a) {
    float v;
    asm volatile("ld.volatile.shared.f32 %0, [%1];" : "=f"(v) : "r"(a) : "memory");
    return v;
}
__device__ __forceinline__ float4 lds_vol4(uint32_t a) {
    float4 v;
    asm volatile("ld.volatile.shared.v4.f32 {%0,%1,%2,%3}, [%4];"
                 : "=f"(v.x), "=f"(v.y), "=f"(v.z), "=f"(v.w) : "r"(a) : "memory");
    return v;
}
__device__ __forceinline__ void sts_f32(uint32_t a, float v) {
    asm volatile("st.volatile.shared.f32 [%0], %1;" :: "r"(a), "f"(v) : "memory");
}
__device__ __forceinline__ void sts4_same(uint32_t a, float v) {
    asm volatile("st.volatile.shared.v4.f32 [%0], {%1,%1,%1,%1};" :: "r"(a), "f"(v) : "memory");
}
__device__ __forceinline__ void sts_cluster(uint32_t a, float v) {
    asm volatile("st.shared::cluster.f32 [%0], %1;" :: "r"(a), "f"(v) : "memory");
}
__device__ __forceinline__ uint32_t mapa_u32(uint32_t a, uint32_t r) {
    uint32_t d;
    asm("mapa.shared::cluster.u32 %0, %1, %2;" : "=r"(d) : "r"(a), "r"(r));
    return d;
}
__device__ __forceinline__ unsigned long long pack2(float a, float b) {
    return (unsigned long long)__float_as_uint(a) |
           ((unsigned long long)__float_as_uint(b) << 32);
}
__device__ __forceinline__ float lo2(unsigned long long v) {
    return __uint_as_float((unsigned)(v & 0xffffffffull));
}
__device__ __forceinline__ float hi2(unsigned long long v) {
    return __uint_as_float((unsigned)(v >> 32));
}
#define CLUSTER_BAR() do { \
    asm volatile("barrier.cluster.arrive.aligned;" ::: "memory"); \
    asm volatile("barrier.cluster.wait.aligned;" ::: "memory"); \
} while (0)

// ---------------------------------------------------------------------------
// K1: init global h buffers: t==0 -> 0.0f, else canary
// ---------------------------------------------------------------------------
__global__ void init_kernel() {
    int idx = blockIdx.x * 256 + threadIdx.x;
    const int total = 3 * (TT + 1) * HID;
    if (idx < total) {
        int t = (idx / HID) % (TT + 1);
        ((float*)g_hbuf)[idx] = (t == 0) ? 0.0f : __int_as_float(CANARY_I);
    }
}

// ---------------------------------------------------------------------------
// K2: layer-0 input projection (+ both biases), permuted
// ---------------------------------------------------------------------------
__global__ void xg0_kernel(const float* __restrict__ x,
                           const float* __restrict__ w_ih0,
                           const float* __restrict__ b_ih0,
                           const float* __restrict__ b_hh0) {
    __shared__ float xs[8][FIN];
    const int t0 = blockIdx.x * 8;
    const int tid = threadIdx.x;

    for (int i = tid; i < 8 * FIN; i += 256) {
        int tt = i / FIN, f = i % FIN;
        xs[tt][f] = x[((size_t)(BATCH - 1) * TT + (t0 + tt)) * FIN + f];
    }
    __syncthreads();

    const int cta = tid >> 3;
    const int jj  = tid & 7;

    for (int q = 0; q < 4; q++) {
        int grow = q * 256 + tid;
        float w[FIN];
        const float4* wr = (const float4*)(w_ih0 + (size_t)grow * FIN);
        #pragma unroll
        for (int i = 0; i < FIN / 4; i++) {
            float4 v = wr[i];
            w[4 * i] = v.x; w[4 * i + 1] = v.y; w[4 * i + 2] = v.z; w[4 * i + 3] = v.w;
        }
        float bb = b_ih0[grow] + b_hh0[grow];
        #pragma unroll
        for (int tt = 0; tt < 8; tt++) {
            float s = bb;
            #pragma unroll
            for (int f = 0; f < FIN; f++) s += w[f] * xs[tt][f];
            g_xg0[t0 + tt][cta][q * 8 + jj] = s;
        }
    }
}

// ---------------------------------------------------------------------------
// K3a: CLUSTER pipeline, FULLY flag-synchronized (no per-step barrier).
// 48 CTAs = 3 clusters of 16. 288 threads: warps 0-7 dot, warp 8 reducer.
// psum: SPSC canary full/empty protocol (producer waits-empty, writes;
// reducer waits-full, reads, resets). self_h: 2-deep parity, DSMEM publish,
// consumer resets; reuse ordered by transitive cross-CTA data dependence.
// ---------------------------------------------------------------------------
__global__ void __launch_bounds__(THR_CL, 1)
lstm_cluster(const float* __restrict__ w_hh0,
             const float* __restrict__ w_ih1, const float* __restrict__ w_hh1,
             const float* __restrict__ b_ih1, const float* __restrict__ b_hh1,
             const float* __restrict__ w_ih2, const float* __restrict__ w_hh2,
             const float* __restrict__ b_ih2, const float* __restrict__ b_hh2) {
    __shared__ __align__(16) float self_h[2][256];
    __shared__ __align__(16) float in_stage[256];
    __shared__ __align__(16) float psum[2][RR][NW];

    const int layer = blockIdx.x >> 4;
    const int cta   = blockIdx.x & 15;
    const int warp  = threadIdx.x >> 5;
    const int lane  = threadIdx.x & 31;
    const float CAN = __int_as_float(CANARY_I);

    // init smem: slot0 = h(0) = 0, slot1 = canary, psum all canary (empty)
    for (int i = threadIdx.x; i < 256; i += THR_CL) {
        self_h[0][i] = 0.0f;
        self_h[1][i] = CAN;
    }
    for (int i = threadIdx.x; i < 2 * RR * NW; i += THR_CL)
        ((float*)psum)[i] = CAN;
    __syncthreads();
    CLUSTER_BAR();

    const float *wih = nullptr, *whh = nullptr, *bih = nullptr, *bhh = nullptr;
    if (layer == 0)      { whh = w_hh0; }
    else if (layer == 1) { wih = w_ih1; whh = w_hh1; bih = b_ih1; bhh = b_hh1; }
    else                 { wih = w_ih2; whh = w_hh2; bih = b_ih2; bhh = b_hh2; }

    if (warp < NW) {
        // ---------------- dot warps ----------------
        const bool self_side = (warp >= 4);
        if (layer == 0 && !self_side) {   // inactive: nothing to do, no loop
            CLUSTER_BAR();
            return;
        }

        const int cs = self_side ? (warp - 4) * CW : warp * CW;
        const float* Wsrc = self_side ? whh : wih;

        unsigned long long w2[64];
        #pragma unroll
        for (int k = 0; k < 2; k++) {
            int grow = ((lane >> 4) + 2 * k) * 256 + cta * CH + (lane & 15);
            const float* wr = Wsrc + (size_t)grow * HID + cs;
            #pragma unroll
            for (int j = 0; j < 32; j++)
                w2[32 * k + j] = pack2(wr[2 * j], wr[2 * j + 1]);
        }

        uint32_t sa0[2], sa1[2], pso[2];
        #pragma unroll
        for (int p = 0; p < 2; p++) {
            sa0[p] = (uint32_t)__cvta_generic_to_shared(&self_h[p][cs + lane]);
            sa1[p] = sa0[p] + 32 * 4;
            pso[p] = (uint32_t)__cvta_generic_to_shared(&psum[p][lane][warp]);
        }

        for (int t = 0; t < TT; t++) {
            const int par = t & 1;
            const float* hb;
            if (self_side) {
                float v0, v1; int got = 0;
                do {
                    if (!(got & 1)) { v0 = lds_vol(sa0[par]); if (__float_as_int(v0) != CANARY_I) got |= 1; }
                    if (!(got & 2)) { v1 = lds_vol(sa1[par]); if (__float_as_int(v1) != CANARY_I) got |= 2; }
                } while (got != 3);
                __syncwarp();
                hb = &self_h[par][cs];
            } else {
                const float* p0 = &g_hbuf[layer - 1][t + 1][cs + lane];
                const float* p1 = p0 + 32;
                float v0, v1; int got = 0;
                do {
                    if (!(got & 1)) { v0 = poll_ld(p0); if (__float_as_int(v0) != CANARY_I) got |= 1; }
                    if (!(got & 2)) { v1 = poll_ld(p1); if (__float_as_int(v1) != CANARY_I) got |= 2; }
                } while (got != 3);
                in_stage[cs + lane] = v0;
                in_stage[cs + lane + 32] = v1;
                __syncwarp();
                hb = &in_stage[cs];
            }

            unsigned long long a00 = 0, a01 = 0, a10 = 0, a11 = 0;
            #pragma unroll
            for (int jj = 0; jj < 16; jj++) {
                ulonglong2 hv = *(const ulonglong2*)(hb + 4 * jj);
                FMA2(a00, w2[2 * jj],      hv.x, a00);
                FMA2(a01, w2[2 * jj + 1],  hv.y, a01);
                FMA2(a10, w2[32 + 2 * jj], hv.x, a10);
                FMA2(a11, w2[33 + 2 * jj], hv.y, a11);
            }
            if (self_side) {
                // all lanes finished reading hb before the reset
                __syncwarp();
                sts_f32(sa0[par], CAN);    // reset BEFORE psum store: this
                sts_f32(sa1[par], CAN);    // ordering is load-bearing (see hdr)
            }
            float pa = (lo2(a00) + hi2(a00)) + (lo2(a01) + hi2(a01));
            float pb = (lo2(a10) + hi2(a10)) + (lo2(a11) + hi2(a11));

            // SPSC: wait until reducer consumed the slot (reset to canary)
            float e;
            do { e = lds_vol(pso[par]); } while (__float_as_int(e) != CANARY_I);
            do { e = lds_vol(pso[par] + 32 * NW * 4); } while (__float_as_int(e) != CANARY_I);
            sts_f32(pso[par], pa);
            sts_f32(pso[par] + 32 * NW * 4, pb);
        }
        CLUSTER_BAR();
        return;
    }

    // ---------------- reducer warp (warp 8) ----------------
    {
        int grow0 = (lane >> 4) * 256 + cta * CH + (lane & 15);
        int grow1 = grow0 + 2 * 256;
        float b0 = 0.0f, b1 = 0.0f;
        int xi0 = 0, xi1 = 0;
        if (layer > 0) {
            b0 = bih[grow0] + bhh[grow0];
            b1 = bih[grow1] + bhh[grow1];
        } else {
            int r0 = grow0 & 255, r1 = grow1 & 255;
            xi0 = ((r0 >> 3) << 5) + ((grow0 >> 8) << 3) + (r0 & 7);
            xi1 = ((r1 >> 3) << 5) + ((grow1 >> 8) << 3) + (r1 & 7);
        }

        uint32_t q0[2], q2[2];
        #pragma unroll
        for (int p = 0; p < 2; p++) {
            q0[p] = (uint32_t)__cvta_generic_to_shared(&psum[p][lane][0]);
            q2[p] = (uint32_t)__cvta_generic_to_shared(&psum[p][lane + 32][0]);
        }
        const int j = lane & 15;
        const int pbase = (lane >> 4) * 8;

        // precompute DSMEM publish addresses: 2 parities x 8 peers (mapa
        // hoisted out of the loop)
        uint32_t hrem[2][8];
        #pragma unroll
        for (int p = 0; p < 2; p++) {
            uint32_t la = (uint32_t)__cvta_generic_to_shared(&self_h[p][cta * CH + j]);
            #pragma unroll
            for (int i = 0; i < 8; i++)
                hrem[p][i] = mapa_u32(la, pbase + i);
        }
        const float CANr = __int_as_float(CANARY_I);

        float creg = 0.0f;

        for (int t = 0; t < TT; t++) {
            const int par = t & 1;
            float xga = 0.0f, xgb = 0.0f;
            if (layer == 0) {
                const float* xf = (const float*)g_xg0 + (size_t)t * 1024;
                xga = __ldg(xf + xi0);
                xgb = __ldg(xf + xi1);
            }

            float rs0, rs1;
            if (layer == 0) {
                float4 A1, B1;
                int got = 0;
                do {
                    if (!(got & 1)) {
                        A1 = lds_vol4(q0[par] + 16);
                        if (__float_as_int(A1.x) != CANARY_I && __float_as_int(A1.y) != CANARY_I &&
                            __float_as_int(A1.z) != CANARY_I && __float_as_int(A1.w) != CANARY_I) got |= 1;
                    }
                    if (!(got & 2)) {
                        B1 = lds_vol4(q2[par] + 16);
                        if (__float_as_int(B1.x) != CANARY_I && __float_as_int(B1.y) != CANARY_I &&
                            __float_as_int(B1.z) != CANARY_I && __float_as_int(B1.w) != CANARY_I) got |= 2;
                    }
                } while (got != 3);
                rs0 = (A1.x + A1.y) + (A1.z + A1.w) + xga;
                rs1 = (B1.x + B1.y) + (B1.z + B1.w) + xgb;
                sts4_same(q0[par] + 16, CANr);
                sts4_same(q2[par] + 16, CANr);
            } else {
                float4 A0, A1, B0, B1;
                int got = 0;
                do {
                    if (!(got & 1)) {
                        A0 = lds_vol4(q0[par]);
                        if (__float_as_int(A0.x) != CANARY_I && __float_as_int(A0.y) != CANARY_I &&
                            __float_as_int(A0.z) != CANARY_I && __float_as_int(A0.w) != CANARY_I) got |= 1;
                    }
                    if (!(got & 2)) {
                        A1 = lds_vol4(q0[par] + 16);
                        if (__float_as_int(A1.x) != CANARY_I && __float_as_int(A1.y) != CANARY_I &&
                            __float_as_int(A1.z) != CANARY_I && __float_as_int(A1.w) != CANARY_I) got |= 2;
                    }
                    if (!(got & 4)) {
                        B0 = lds_vol4(q2[par]);
                        if (__float_as_int(B0.x) != CANARY_I && __float_as_int(B0.y) != CANARY_I &&
                            __float_as_int(B0.z) != CANARY_I && __float_as_int(B0.w) != CANARY_I) got |= 4;
                    }
                    if (!(got & 8)) {
                        B1 = lds_vol4(q2[par] + 16);
                        if (__float_as_int(B1.x) != CANARY_I && __float_as_int(B1.y) != CANARY_I &&
                            __float_as_int(B1.z) != CANARY_I && __float_as_int(B1.w) != CANARY_I) got |= 8;
                    }
                } while (got != 15);
                rs0 = ((A0.x + A0.y) + (A0.z + A0.w)) + ((A1.x + A1.y) + (A1.z + A1.w)) + b0;
                rs1 = ((B0.x + B0.y) + (B0.z + B0.w)) + ((B1.x + B1.y) + (B1.z + B1.w)) + b1;
                sts4_same(q0[par], CANr); sts4_same(q0[par] + 16, CANr);
                sts4_same(q2[par], CANr); sts4_same(q2[par] + 16, CANr);
            }

            // gates: i = row j, f = row j+16 (rs0); g = row 32+j, o = row 48+j (rs1)
            float vi = __shfl_sync(0xffffffffu, rs0, j);
            float vf = __shfl_sync(0xffffffffu, rs0, j + 16);
            float vg = __shfl_sync(0xffffffffu, rs1, j);
            float vo = __shfl_sync(0xffffffffu, rs1, j + 16);

            float i_ = sig_fast(vi);
            float f_ = sig_fast(vf);
            float g_ = tanh_fast(vg);
            float o_ = sig_fast(vo);
            creg = f_ * creg + i_ * g_;
            float h = o_ * tanh_fast(creg);

            // publish h(t+1): DSMEM to all 16 peers (precomputed addrs), then L2
            const uint32_t* hr = hrem[par ^ 1];
            #pragma unroll
            for (int i = 0; i < 8; i++)
                sts_cluster(hr[i], h);
            if (lane < 16)
                st_vol(&g_hbuf[layer][t + 1][cta * CH + j], h);
        }
        CLUSTER_BAR();
    }
}

// ---------------------------------------------------------------------------
// K3b: FALLBACK global-L2 pipeline (proven R2 kernel, 1120us)
// ---------------------------------------------------------------------------
__global__ void __launch_bounds__(256, 1)
lstm_pipeline(const float* __restrict__ w_hh0,
              const float* __restrict__ w_ih1, const float* __restrict__ w_hh1,
              const float* __restrict__ b_ih1, const float* __restrict__ b_hh1,
              const float* __restrict__ w_ih2, const float* __restrict__ w_hh2,
              const float* __restrict__ b_ih2, const float* __restrict__ b_hh2) {
    __shared__ float harr[512];
    __shared__ float psum[2][8][32];

    const int layer = blockIdx.x >> 5;
    const int cta   = blockIdx.x & 31;
    const int warp  = threadIdx.x >> 5;
    const int lane  = threadIdx.x & 31;

    const float *wih = nullptr, *whh = nullptr, *bih = nullptr, *bhh = nullptr;
    if (layer == 0)      { whh = w_hh0; }
    else if (layer == 1) { wih = w_ih1; whh = w_hh1; bih = b_ih1; bhh = b_hh1; }
    else                 { wih = w_ih2; whh = w_hh2; bih = b_ih2; bhh = b_hh2; }

    const int grow = (lane >> 3) * HID + cta * CHUNK + (lane & 7);

    unsigned long long w2[32];
    if (layer == 0) {
        const int C = warp * 32;
        #pragma unroll
        for (int j = 0; j < 16; j++)
            w2[j] = pack2(whh[(size_t)grow * HID + C + 2 * j],
                          whh[(size_t)grow * HID + C + 2 * j + 1]);
    } else {
        const int C = warp * 64;
        #pragma unroll
        for (int j = 0; j < 32; j++) {
            int c = C + 2 * j;
            float a, b;
            if (c < HID) { a = wih[(size_t)grow * HID + c];
                           b = wih[(size_t)grow * HID + c + 1]; }
            else         { a = whh[(size_t)grow * HID + c - HID];
                           b = whh[(size_t)grow * HID + c - HID + 1]; }
            w2[j] = pack2(a, b);
        }
    }

    float biasr = 0.0f;
    if (warp == 7 && layer > 0) biasr = bih[grow] + bhh[grow];

    float creg = 0.0f;
    int par = 0;

    for (int t = 0; t < TT; t++) {
        float xgv = 0.0f;
        if (layer == 0 && warp == 7) xgv = g_xg0[t][cta][lane];

        if (layer == 0) {
            const float* p = &g_hbuf[0][t][warp * 32 + lane];
            float v;
            do { v = poll_ld(p); } while (__float_as_int(v) == CANARY_I);
            harr[warp * 32 + lane] = v;
        } else if (warp < 4) {
            const float* p0 = &g_hbuf[layer - 1][t + 1][warp * 64 + lane];
            const float* p1 = p0 + 32;
            float v0, v1; int got = 0;
            do {
                if (!(got & 1)) { v0 = poll_ld(p0); if (__float_as_int(v0) != CANARY_I) got |= 1; }
                if (!(got & 2)) { v1 = poll_ld(p1); if (__float_as_int(v1) != CANARY_I) got |= 2; }
            } while (got != 3);
            harr[warp * 64 + lane] = v0;
            harr[warp * 64 + 32 + lane] = v1;
        } else {
            const float* p0 = &g_hbuf[layer][t][(warp - 4) * 64 + lane];
            const float* p1 = p0 + 32;
            float v0, v1; int got = 0;
            do {
                if (!(got & 1)) { v0 = poll_ld(p0); if (__float_as_int(v0) != CANARY_I) got |= 1; }
                if (!(got & 2)) { v1 = poll_ld(p1); if (__float_as_int(v1) != CANARY_I) got |= 2; }
            } while (got != 3);
            harr[warp * 64 + lane] = v0;
            harr[warp * 64 + 32 + lane] = v1;
        }
        __syncwarp(0xffffffffu);

        unsigned long long acc0 = 0ull, acc1 = 0ull;
        if (layer == 0) {
            const float* hb = &harr[warp * 32];
            #pragma unroll
            for (int i = 0; i < 8; i++) {
                ulonglong2 hv = *(const ulonglong2*)&hb[4 * i];
                FMA2(acc0, w2[2 * i],     hv.x, acc0);
                FMA2(acc1, w2[2 * i + 1], hv.y, acc1);
            }
        } else {
            const float* hb = &harr[warp * 64];
            #pragma unroll
            for (int i = 0; i < 16; i++) {
                ulonglong2 hv = *(const ulonglong2*)&hb[4 * i];
                FMA2(acc0, w2[2 * i],     hv.x, acc0);
                FMA2(acc1, w2[2 * i + 1], hv.y, acc1);
            }
        }
        float partial = (lo2(acc0) + hi2(acc0)) + (lo2(acc1) + hi2(acc1));
        psum[par][warp][lane] = partial;

        __syncthreads();

        if (warp == 7) {
            float rs = psum[par][0][lane] + psum[par][1][lane]
                     + psum[par][2][lane] + psum[par][3][lane]
                     + psum[par][4][lane] + psum[par][5][lane]
                     + psum[par][6][lane] + psum[par][7][lane];
            rs += (layer == 0) ? xgv : biasr;

            int j = lane & 7;
            float vi = __shfl_sync(0xffffffffu, rs, j);
            float vf = __shfl_sync(0xffffffffu, rs, j + 8);
            float vg = __shfl_sync(0xffffffffu, rs, j + 16);
            float vo = __shfl_sync(0xffffffffu, rs, j + 24);

            float i_ = sig_fast(vi);
            float f_ = sig_fast(vf);
            float g_ = tanh_fast(vg);
            float o_ = sig_fast(vo);
            creg = f_ * creg + i_ * g_;
            float h = o_ * tanh_fast(creg);
            if (lane < CHUNK)
                st_vol(&g_hbuf[layer][t + 1][cta * CHUNK + lane], h);
        }
        par ^= 1;
    }
}

// ---------------------------------------------------------------------------
// K4: classifier GEMM, grid (128,3) x 512 threads
// ---------------------------------------------------------------------------
__global__ void __launch_bounds__(512)
classify_kernel(const float* __restrict__ wlin,
                const float* __restrict__ blin) {
    __shared__ float hs[8][HID];
    const int t0 = blockIdx.x * 8;
    const int tid = threadIdx.x;

    for (int i = tid; i < 8 * HID; i += 512) {
        int tt = i >> 8, k = i & 255;
        hs[tt][k] = g_hbuf[2][t0 + tt + 1][k];
    }
    __syncthreads();

    int spk = blockIdx.y * 512 + tid;
    if (spk < NSPK) {
        const unsigned long long* wr =
            (const unsigned long long*)(wlin + (size_t)spk * HID);
        unsigned long long acc[8];
        #pragma unroll
        for (int tt = 0; tt < 8; tt++) acc[tt] = 0ull;

        #pragma unroll 8
        for (int p = 0; p < HID / 2; p += 2) {
            ulonglong2 wv = *(const ulonglong2*)&wr[p];
            #pragma unroll
            for (int tt = 0; tt < 8; tt++) {
                ulonglong2 hv = *(const ulonglong2*)&hs[tt][2 * p];
                FMA2(acc[tt], wv.x, hv.x, acc[tt]);
                FMA2(acc[tt], wv.y, hv.y, acc[tt]);
            }
        }
        float bb = blin[spk];
        #pragma unroll
        for (int tt = 0; tt < 8; tt++) {
            g_logits[(size_t)(t0 + tt) * NSPK + spk] =
                lo2(acc[tt]) + hi2(acc[tt]) + bb;
        }
    }
}

// ---------------------------------------------------------------------------
// K5: row-wise log_softmax
// ---------------------------------------------------------------------------
__global__ void softmax_kernel(float* __restrict__ out) {
    const int t = blockIdx.x;
    const int tid = threadIdx.x;
    __shared__ float red[256];
    const float* row = g_logits + (size_t)t * NSPK;

    float mx = -INFINITY;
    for (int s = tid; s < NSPK; s += 256) mx = fmaxf(mx, row[s]);
    red[tid] = mx; __syncthreads();
    for (int o = 128; o > 0; o >>= 1) {
        if (tid < o) red[tid] = fmaxf(red[tid], red[tid + o]);
        __syncthreads();
    }
    mx = red[0]; __syncthreads();

    float sum = 0.0f;
    for (int s = tid; s < NSPK; s += 256) sum += expf(row[s] - mx);
    red[tid] = sum; __syncthreads();
    for (int o = 128; o > 0; o >>= 1) {
        if (tid < o) red[tid] += red[tid + o];
        __syncthreads();
    }
    float lse = mx + logf(red[0]);

    for (int s = tid; s < NSPK; s += 256) out[(size_t)t * NSPK + s] = row[s] - lse;
}

// ---------------------------------------------------------------------------
extern "C" void kernel_launch(void* const* d_in, const int* in_sizes, int n_in,
                              void* d_out, int out_size) {
    const float* x     = (const float*)d_in[0];
    const float* w_ih0 = (const float*)d_in[1];
    const float* w_hh0 = (const float*)d_in[2];
    const float* b_ih0 = (const float*)d_in[3];
    const float* b_hh0 = (const float*)d_in[4];
    const float* w_ih1 = (const float*)d_in[5];
    const float* w_hh1 = (const float*)d_in[6];
    const float* b_ih1 = (const float*)d_in[7];
    const float* b_hh1 = (const float*)d_in[8];
    const float* w_ih2 = (const float*)d_in[9];
    const float* w_hh2 = (const float*)d_in[10];
    const float* b_ih2 = (const float*)d_in[11];
    const float* b_hh2 = (const float*)d_in[12];
    const float* w_lin = (const float*)d_in[13];
    const float* b_lin = (const float*)d_in[14];
    float* out = (float*)d_out;

    const int init_total = 3 * (TT + 1) * HID;
    init_kernel<<<(init_total + 255) / 256, 256>>>();
    xg0_kernel<<<TT / 8, 256>>>(x, w_ih0, b_ih0, b_hh0);

    // Prefer 16-CTA-cluster DSMEM pipeline; fall back to global-L2 version.
    cudaFuncSetAttribute(lstm_cluster,
                         cudaFuncAttributeNonPortableClusterSizeAllowed, 1);
    cudaLaunchConfig_t cfg = {};
    cfg.gridDim  = dim3(3 * GC, 1, 1);
    cfg.blockDim = dim3(THR_CL, 1, 1);
    cfg.dynamicSmemBytes = 0;
    cudaLaunchAttribute at[1];
    at[0].id = cudaLaunchAttributeClusterDimension;
    at[0].val.clusterDim.x = GC;
    at[0].val.clusterDim.y = 1;
    at[0].val.clusterDim.z = 1;
    cfg.attrs = at;
    cfg.numAttrs = 1;

    int maxc = 0;
    cudaError_t qe = cudaOccupancyMaxPotentialClusterSize(&maxc, lstm_cluster, &cfg);

    bool launched = false;
    if (qe == cudaSuccess && maxc >= GC) {
        cudaError_t le = cudaLaunchKernelEx(&cfg, lstm_cluster, w_hh0,
                                            w_ih1, w_hh1, b_ih1, b_hh1,
                                            w_ih2, w_hh2, b_ih2, b_hh2);
        launched = (le == cudaSuccess);
        if (!launched) (void)cudaGetLastError();   // clear sticky error
    }
    if (!launched) {
        lstm_pipeline<<<NCTA, 256>>>(w_hh0,
                                     w_ih1, w_hh1, b_ih1, b_hh1,
                                     w_ih2, w_hh2, b_ih2, b_hh2);
    }

    classify_kernel<<<dim3(TT / 8, 3), 512>>>(w_lin, b_lin);
    softmax_kernel<<<TT, 256>>>(out);
}

// round 13
// speedup vs baseline: 1.5563x; 1.5563x over previous
#include <cuda_runtime.h>
#include <cuda_bf16.h>
#include <math.h>
#include <stdint.h>

// Problem dims
#define TT    1024
#define HID   256
#define FIN   40
#define NSPK  1251
#define BATCH 64

// Global-fallback pipeline config
#define G      32
#define CHUNK  8
#define ROWS   32
#define NCTA   (3 * G)

// Cluster pipeline config
#define GC     16       // CTAs per layer-cluster
#define RR     64       // gate rows per CTA
#define CH     16       // h-indices per CTA
#define CW     64       // columns per dot warp
#define NW     8        // dot warps (warp 8 = reducer)
#define THR_CL 288

#define CANARY_I 0x7fb0beef

__device__ float g_hbuf[3][TT + 1][HID];
__device__ float g_xg0[TT][32][32];
__device__ float g_logits[TT * NSPK];

#define FMA2(d, a, b, c) \
    asm("fma.rn.f32x2 %0, %1, %2, %3;" : "=l"(d) : "l"(a), "l"(b), "l"(c))

__device__ __forceinline__ float tanh_fast(float x) {
    float r;
    asm("tanh.approx.f32 %0, %1;" : "=f"(r) : "f"(x));
    return r;
}
__device__ __forceinline__ float sig_fast(float x) {
    return 0.5f * tanh_fast(0.5f * x) + 0.5f;
}
__device__ __forceinline__ float poll_ld(const float* p) {
    float v;
    asm volatile("ld.volatile.global.f32 %0, [%1];" : "=f"(v) : "l"(p) : "memory");
    return v;
}
__device__ __forceinline__ void st_vol(float* p, float v) {
    asm volatile("st.volatile.global.f32 [%0], %1;" :: "l"(p), "f"(v) : "memory");
}
__device__ __forceinline__ float lds_vol(uint32_t a) {
    float v;
    asm volatile("ld.volatile.shared.f32 %0, [%1];" : "=f"(v) : "r"(a) : "memory");
    return v;
}
__device__ __forceinline__ void sts_f32(uint32_t a, float v) {
    asm volatile("st.shared.f32 [%0], %1;" :: "r"(a), "f"(v) : "memory");
}
__device__ __forceinline__ void sts_cluster(uint32_t a, float v) {
    asm volatile("st.shared::cluster.f32 [%0], %1;" :: "r"(a), "f"(v) : "memory");
}
__device__ __forceinline__ uint32_t mapa_u32(uint32_t a, uint32_t r) {
    uint32_t d;
    asm("mapa.shared::cluster.u32 %0, %1, %2;" : "=r"(d) : "r"(a), "r"(r));
    return d;
}
__device__ __forceinline__ void mbar_init(uint32_t a, uint32_t count) {
    asm volatile("mbarrier.init.shared.b64 [%0], %1;" :: "r"(a), "r"(count) : "memory");
}
__device__ __forceinline__ void mbar_arrive_remote(uint32_t a) {
    asm volatile("mbarrier.arrive.shared::cluster.b64 _, [%0];" :: "r"(a) : "memory");
}
// Sleeping parity wait, cluster-scope acquire (remote release-arrives).
#define MBAR_WAIT_CL(addr, par_) do { \
    uint32_t _done; \
    do { \
        asm volatile("{\n\t.reg .pred p;\n\t" \
            "mbarrier.try_wait.parity.acquire.cluster.shared::cta.b64 p, [%1], %2, 0x989680;\n\t" \
            "selp.b32 %0, 1, 0, p;\n\t}" \
            : "=r"(_done) : "r"((uint32_t)(addr)), "r"((uint32_t)(par_)) : "memory"); \
    } while (!_done); \
} while (0)

__device__ __forceinline__ unsigned long long pack2(float a, float b) {
    return (unsigned long long)__float_as_uint(a) |
           ((unsigned long long)__float_as_uint(b) << 32);
}
__device__ __forceinline__ float lo2(unsigned long long v) {
    return __uint_as_float((unsigned)(v & 0xffffffffull));
}
__device__ __forceinline__ float hi2(unsigned long long v) {
    return __uint_as_float((unsigned)(v >> 32));
}
#define CLUSTER_BAR() do { \
    asm volatile("barrier.cluster.arrive.aligned;" ::: "memory"); \
    asm volatile("barrier.cluster.wait.aligned;" ::: "memory"); \
} while (0)

// ---------------------------------------------------------------------------
// K1: init global h buffers: t==0 -> 0.0f, else canary
// ---------------------------------------------------------------------------
__global__ void init_kernel() {
    int idx = blockIdx.x * 256 + threadIdx.x;
    const int total = 3 * (TT + 1) * HID;
    if (idx < total) {
        int t = (idx / HID) % (TT + 1);
        ((float*)g_hbuf)[idx] = (t == 0) ? 0.0f : __int_as_float(CANARY_I);
    }
}

// ---------------------------------------------------------------------------
// K2: layer-0 input projection (+ both biases), permuted
// ---------------------------------------------------------------------------
__global__ void xg0_kernel(const float* __restrict__ x,
                           const float* __restrict__ w_ih0,
                           const float* __restrict__ b_ih0,
                           const float* __restrict__ b_hh0) {
    __shared__ float xs[8][FIN];
    const int t0 = blockIdx.x * 8;
    const int tid = threadIdx.x;

    for (int i = tid; i < 8 * FIN; i += 256) {
        int tt = i / FIN, f = i % FIN;
        xs[tt][f] = x[((size_t)(BATCH - 1) * TT + (t0 + tt)) * FIN + f];
    }
    __syncthreads();

    const int cta = tid >> 3;
    const int jj  = tid & 7;

    for (int q = 0; q < 4; q++) {
        int grow = q * 256 + tid;
        float w[FIN];
        const float4* wr = (const float4*)(w_ih0 + (size_t)grow * FIN);
        #pragma unroll
        for (int i = 0; i < FIN / 4; i++) {
            float4 v = wr[i];
            w[4 * i] = v.x; w[4 * i + 1] = v.y; w[4 * i + 2] = v.z; w[4 * i + 3] = v.w;
        }
        float bb = b_ih0[grow] + b_hh0[grow];
        #pragma unroll
        for (int tt = 0; tt < 8; tt++) {
            float s = bb;
            #pragma unroll
            for (int f = 0; f < FIN; f++) s += w[f] * xs[tt][f];
            g_xg0[t0 + tt][cta][q * 8 + jj] = s;
        }
    }
}

// ---------------------------------------------------------------------------
// K3a: CLUSTER pipeline (R9 skeleton: ONE __syncthreads per step for psum)
// + mbarrier-based self_h signaling: peers' reducers release-arrive after
// DSMEM publish; self-side dot warps SLEEP in try_wait instead of spinning.
// ---------------------------------------------------------------------------
__global__ void __launch_bounds__(THR_CL, 1)
lstm_cluster(const float* __restrict__ w_hh0,
             const float* __restrict__ w_ih1, const float* __restrict__ w_hh1,
             const float* __restrict__ b_ih1, const float* __restrict__ b_hh1,
             const float* __restrict__ w_ih2, const float* __restrict__ w_hh2,
             const float* __restrict__ b_ih2, const float* __restrict__ b_hh2) {
    __shared__ __align__(16) float self_h[2][256];
    __shared__ __align__(16) float in_stage[256];
    __shared__ __align__(16) float psum[2][RR][NW];
    __shared__ __align__(8) unsigned long long mbar_h;

    const int layer = blockIdx.x >> 4;
    const int cta   = blockIdx.x & 15;
    const int warp  = threadIdx.x >> 5;
    const int lane  = threadIdx.x & 31;

    const uint32_t mb_local = (uint32_t)__cvta_generic_to_shared(&mbar_h);

    // init smem: slot0 = h(0) = 0; mbarrier expects 16 arrivals/phase
    for (int i = threadIdx.x; i < 256; i += THR_CL) {
        self_h[0][i] = 0.0f;
        self_h[1][i] = 0.0f;
    }
    if (threadIdx.x == 0) mbar_init(mb_local, 16);
    __syncthreads();
    CLUSTER_BAR();   // all CTAs' mbarriers initialized before any remote arrive

    const float *wih = nullptr, *whh = nullptr, *bih = nullptr, *bhh = nullptr;
    if (layer == 0)      { whh = w_hh0; }
    else if (layer == 1) { wih = w_ih1; whh = w_hh1; bih = b_ih1; bhh = b_hh1; }
    else                 { wih = w_ih2; whh = w_hh2; bih = b_ih2; bhh = b_hh2; }

    if (warp < NW) {
        // ---------------- dot warps ----------------
        const bool self_side = (warp >= 4);
        const bool active = !(layer == 0 && !self_side);

        const int cs = self_side ? (warp - 4) * CW : warp * CW;
        const float* Wsrc = self_side ? whh : wih;

        unsigned long long w2[64];
        if (active) {
            #pragma unroll
            for (int k = 0; k < 2; k++) {
                int grow = ((lane >> 4) + 2 * k) * 256 + cta * CH + (lane & 15);
                const float* wr = Wsrc + (size_t)grow * HID + cs;
                #pragma unroll
                for (int j = 0; j < 32; j++)
                    w2[32 * k + j] = pack2(wr[2 * j], wr[2 * j + 1]);
            }
        }

        uint32_t pso[2];
        #pragma unroll
        for (int p = 0; p < 2; p++)
            pso[p] = (uint32_t)__cvta_generic_to_shared(&psum[p][lane][warp]);

        for (int t = 0; t < TT; t++) {
            const int par = t & 1;
            if (active) {
                const float* hb;
                if (self_side) {
                    if (t > 0)
                        MBAR_WAIT_CL(mb_local, (uint32_t)((t - 1) & 1));  // sleep
                    hb = &self_h[par][cs];
                } else {
                    const float* p0 = &g_hbuf[layer - 1][t + 1][cs + lane];
                    const float* p1 = p0 + 32;
                    float v0, v1; int got = 0;
                    do {
                        if (!(got & 1)) { v0 = poll_ld(p0); if (__float_as_int(v0) != CANARY_I) got |= 1; }
                        if (!(got & 2)) { v1 = poll_ld(p1); if (__float_as_int(v1) != CANARY_I) got |= 2; }
                    } while (got != 3);
                    in_stage[cs + lane] = v0;
                    in_stage[cs + lane + 32] = v1;
                    __syncwarp();
                    hb = &in_stage[cs];
                }

                unsigned long long a00 = 0, a01 = 0, a10 = 0, a11 = 0;
                #pragma unroll
                for (int jj = 0; jj < 16; jj++) {
                    ulonglong2 hv = *(const ulonglong2*)(hb + 4 * jj);
                    FMA2(a00, w2[2 * jj],      hv.x, a00);
                    FMA2(a01, w2[2 * jj + 1],  hv.y, a01);
                    FMA2(a10, w2[32 + 2 * jj], hv.x, a10);
                    FMA2(a11, w2[33 + 2 * jj], hv.y, a11);
                }
                float pa = (lo2(a00) + hi2(a00)) + (lo2(a01) + hi2(a01));
                float pb = (lo2(a10) + hi2(a10)) + (lo2(a11) + hi2(a11));
                sts_f32(pso[par], pa);
                sts_f32(pso[par] + 32 * NW * 4, pb);
            }
            __syncthreads();   // B(t): psum(t) visible; reducer consumed psum(t-1)
        }
        CLUSTER_BAR();
        return;
    }

    // ---------------- reducer warp (warp 8) ----------------
    {
        int grow0 = (lane >> 4) * 256 + cta * CH + (lane & 15);
        int grow1 = grow0 + 2 * 256;
        float b0 = 0.0f, b1 = 0.0f;
        int xi0 = 0, xi1 = 0;
        if (layer > 0) {
            b0 = bih[grow0] + bhh[grow0];
            b1 = bih[grow1] + bhh[grow1];
        } else {
            int r0 = grow0 & 255, r1 = grow1 & 255;
            xi0 = ((r0 >> 3) << 5) + ((grow0 >> 8) << 3) + (r0 & 7);
            xi1 = ((r1 >> 3) << 5) + ((grow1 >> 8) << 3) + (r1 & 7);
        }

        const int j = lane & 15;
        const int pbase = (lane >> 4) * 8;

        // precompute DSMEM publish addresses: 2 parities x 8 peers
        uint32_t hrem[2][8];
        #pragma unroll
        for (int p = 0; p < 2; p++) {
            uint32_t la = (uint32_t)__cvta_generic_to_shared(&self_h[p][cta * CH + j]);
            #pragma unroll
            for (int i = 0; i < 8; i++)
                hrem[p][i] = mapa_u32(la, pbase + i);
        }
        // remote mbarrier address: lane i (i<16) arrives on CTA i's mbar
        uint32_t mb_rem = (lane < 16) ? mapa_u32(mb_local, lane) : 0;

        float creg = 0.0f;

        for (int t = 0; t < TT; t++) {
            const int par = t & 1;
            float xga = 0.0f, xgb = 0.0f;
            if (layer == 0) {
                const float* xf = (const float*)g_xg0 + (size_t)t * 1024;
                xga = __ldg(xf + xi0);
                xgb = __ldg(xf + xi1);
            }

            __syncthreads();   // B(t): dot warps' psum(t) now visible

            float rs0, rs1;
            if (layer == 0) {
                float4 A1 = *(const float4*)&psum[par][lane][4];
                float4 B1 = *(const float4*)&psum[par][lane + 32][4];
                rs0 = (A1.x + A1.y) + (A1.z + A1.w) + xga;
                rs1 = (B1.x + B1.y) + (B1.z + B1.w) + xgb;
            } else {
                float4 A0 = *(const float4*)&psum[par][lane][0];
                float4 A1 = *(const float4*)&psum[par][lane][4];
                float4 B0 = *(const float4*)&psum[par][lane + 32][0];
                float4 B1 = *(const float4*)&psum[par][lane + 32][4];
                rs0 = ((A0.x + A0.y) + (A0.z + A0.w)) + ((A1.x + A1.y) + (A1.z + A1.w)) + b0;
                rs1 = ((B0.x + B0.y) + (B0.z + B0.w)) + ((B1.x + B1.y) + (B1.z + B1.w)) + b1;
            }

            // gates: i = row j, f = row j+16 (rs0); g = row 32+j, o = row 48+j (rs1)
            float vi = __shfl_sync(0xffffffffu, rs0, j);
            float vf = __shfl_sync(0xffffffffu, rs0, j + 16);
            float vg = __shfl_sync(0xffffffffu, rs1, j);
            float vo = __shfl_sync(0xffffffffu, rs1, j + 16);

            float i_ = sig_fast(vi);
            float f_ = sig_fast(vf);
            float g_ = tanh_fast(vg);
            float o_ = sig_fast(vo);
            creg = f_ * creg + i_ * g_;
            float h = o_ * tanh_fast(creg);

            // publish h(t+1): DSMEM data to all 16 peers, then L2, then
            // release-arrive on every peer's mbarrier (signals phase t)
            const uint32_t* hr = hrem[par ^ 1];
            #pragma unroll
            for (int i = 0; i < 8; i++)
                sts_cluster(hr[i], h);
            if (lane < 16)
                st_vol(&g_hbuf[layer][t + 1][cta * CH + j], h);
            __syncwarp();                   // order all lanes' stores
            if (lane < 16)
                mbar_arrive_remote(mb_rem); // 16 arrivals per peer per step
        }
        CLUSTER_BAR();
    }
}

// ---------------------------------------------------------------------------
// K3b: FALLBACK global-L2 pipeline (proven R2 kernel, 1120us)
// ---------------------------------------------------------------------------
__global__ void __launch_bounds__(256, 1)
lstm_pipeline(const float* __restrict__ w_hh0,
              const float* __restrict__ w_ih1, const float* __restrict__ w_hh1,
              const float* __restrict__ b_ih1, const float* __restrict__ b_hh1,
              const float* __restrict__ w_ih2, const float* __restrict__ w_hh2,
              const float* __restrict__ b_ih2, const float* __restrict__ b_hh2) {
    __shared__ float harr[512];
    __shared__ float psum[2][8][32];

    const int layer = blockIdx.x >> 5;
    const int cta   = blockIdx.x & 31;
    const int warp  = threadIdx.x >> 5;
    const int lane  = threadIdx.x & 31;

    const float *wih = nullptr, *whh = nullptr, *bih = nullptr, *bhh = nullptr;
    if (layer == 0)      { whh = w_hh0; }
    else if (layer == 1) { wih = w_ih1; whh = w_hh1; bih = b_ih1; bhh = b_hh1; }
    else                 { wih = w_ih2; whh = w_hh2; bih = b_ih2; bhh = b_hh2; }

    const int grow = (lane >> 3) * HID + cta * CHUNK + (lane & 7);

    unsigned long long w2[32];
    if (layer == 0) {
        const int C = warp * 32;
        #pragma unroll
        for (int j = 0; j < 16; j++)
            w2[j] = pack2(whh[(size_t)grow * HID + C + 2 * j],
                          whh[(size_t)grow * HID + C + 2 * j + 1]);
    } else {
        const int C = warp * 64;
        #pragma unroll
        for (int j = 0; j < 32; j++) {
            int c = C + 2 * j;
            float a, b;
            if (c < HID) { a = wih[(size_t)grow * HID + c];
                           b = wih[(size_t)grow * HID + c + 1]; }
            else         { a = whh[(size_t)grow * HID + c - HID];
                           b = whh[(size_t)grow * HID + c - HID + 1]; }
            w2[j] = pack2(a, b);
        }
    }

    float biasr = 0.0f;
    if (warp == 7 && layer > 0) biasr = bih[grow] + bhh[grow];

    float creg = 0.0f;
    int par = 0;

    for (int t = 0; t < TT; t++) {
        float xgv = 0.0f;
        if (layer == 0 && warp == 7) xgv = g_xg0[t][cta][lane];

        if (layer == 0) {
            const float* p = &g_hbuf[0][t][warp * 32 + lane];
            float v;
            do { v = poll_ld(p); } while (__float_as_int(v) == CANARY_I);
            harr[warp * 32 + lane] = v;
        } else if (warp < 4) {
            const float* p0 = &g_hbuf[layer - 1][t + 1][warp * 64 + lane];
            const float* p1 = p0 + 32;
            float v0, v1; int got = 0;
            do {
                if (!(got & 1)) { v0 = poll_ld(p0); if (__float_as_int(v0) != CANARY_I) got |= 1; }
                if (!(got & 2)) { v1 = poll_ld(p1); if (__float_as_int(v1) != CANARY_I) got |= 2; }
            } while (got != 3);
            harr[warp * 64 + lane] = v0;
            harr[warp * 64 + 32 + lane] = v1;
        } else {
            const float* p0 = &g_hbuf[layer][t][(warp - 4) * 64 + lane];
            const float* p1 = p0 + 32;
            float v0, v1; int got = 0;
            do {
                if (!(got & 1)) { v0 = poll_ld(p0); if (__float_as_int(v0) != CANARY_I) got |= 1; }
                if (!(got & 2)) { v1 = poll_ld(p1); if (__float_as_int(v1) != CANARY_I) got |= 2; }
            } while (got != 3);
            harr[warp * 64 + lane] = v0;
            harr[warp * 64 + 32 + lane] = v1;
        }
        __syncwarp(0xffffffffu);

        unsigned long long acc0 = 0ull, acc1 = 0ull;
        if (layer == 0) {
            const float* hb = &harr[warp * 32];
            #pragma unroll
            for (int i = 0; i < 8; i++) {
                ulonglong2 hv = *(const ulonglong2*)&hb[4 * i];
                FMA2(acc0, w2[2 * i],     hv.x, acc0);
                FMA2(acc1, w2[2 * i + 1], hv.y, acc1);
            }
        } else {
            const float* hb = &harr[warp * 64];
            #pragma unroll
            for (int i = 0; i < 16; i++) {
                ulonglong2 hv = *(const ulonglong2*)&hb[4 * i];
                FMA2(acc0, w2[2 * i],     hv.x, acc0);
                FMA2(acc1, w2[2 * i + 1], hv.y, acc1);
            }
        }
        float partial = (lo2(acc0) + hi2(acc0)) + (lo2(acc1) + hi2(acc1));
        psum[par][warp][lane] = partial;

        __syncthreads();

        if (warp == 7) {
            float rs = psum[par][0][lane] + psum[par][1][lane]
                     + psum[par][2][lane] + psum[par][3][lane]
                     + psum[par][4][lane] + psum[par][5][lane]
                     + psum[par][6][lane] + psum[par][7][lane];
            rs += (layer == 0) ? xgv : biasr;

            int j = lane & 7;
            float vi = __shfl_sync(0xffffffffu, rs, j);
            float vf = __shfl_sync(0xffffffffu, rs, j + 8);
            float vg = __shfl_sync(0xffffffffu, rs, j + 16);
            float vo = __shfl_sync(0xffffffffu, rs, j + 24);

            float i_ = sig_fast(vi);
            float f_ = sig_fast(vf);
            float g_ = tanh_fast(vg);
            float o_ = sig_fast(vo);
            creg = f_ * creg + i_ * g_;
            float h = o_ * tanh_fast(creg);
            if (lane < CHUNK)
                st_vol(&g_hbuf[layer][t + 1][cta * CHUNK + lane], h);
        }
        par ^= 1;
    }
}

// ---------------------------------------------------------------------------
// K4: classifier GEMM, grid (128,3) x 512 threads
// ---------------------------------------------------------------------------
__global__ void __launch_bounds__(512)
classify_kernel(const float* __restrict__ wlin,
                const float* __restrict__ blin) {
    __shared__ float hs[8][HID];
    const int t0 = blockIdx.x * 8;
    const int tid = threadIdx.x;

    for (int i = tid; i < 8 * HID; i += 512) {
        int tt = i >> 8, k = i & 255;
        hs[tt][k] = g_hbuf[2][t0 + tt + 1][k];
    }
    __syncthreads();

    int spk = blockIdx.y * 512 + tid;
    if (spk < NSPK) {
        const unsigned long long* wr =
            (const unsigned long long*)(wlin + (size_t)spk * HID);
        unsigned long long acc[8];
        #pragma unroll
        for (int tt = 0; tt < 8; tt++) acc[tt] = 0ull;

        #pragma unroll 8
        for (int p = 0; p < HID / 2; p += 2) {
            ulonglong2 wv = *(const ulonglong2*)&wr[p];
            #pragma unroll
            for (int tt = 0; tt < 8; tt++) {
                ulonglong2 hv = *(const ulonglong2*)&hs[tt][2 * p];
                FMA2(acc[tt], wv.x, hv.x, acc[tt]);
                FMA2(acc[tt], wv.y, hv.y, acc[tt]);
            }
        }
        float bb = blin[spk];
        #pragma unroll
        for (int tt = 0; tt < 8; tt++) {
            g_logits[(size_t)(t0 + tt) * NSPK + spk] =
                lo2(acc[tt]) + hi2(acc[tt]) + bb;
        }
    }
}

// ---------------------------------------------------------------------------
// K5: row-wise log_softmax
// ---------------------------------------------------------------------------
__global__ void softmax_kernel(float* __restrict__ out) {
    const int t = blockIdx.x;
    const int tid = threadIdx.x;
    __shared__ float red[256];
    const float* row = g_logits + (size_t)t * NSPK;

    float mx = -INFINITY;
    for (int s = tid; s < NSPK; s += 256) mx = fmaxf(mx, row[s]);
    red[tid] = mx; __syncthreads();
    for (int o = 128; o > 0; o >>= 1) {
        if (tid < o) red[tid] = fmaxf(red[tid], red[tid + o]);
        __syncthreads();
    }
    mx = red[0]; __syncthreads();

    float sum = 0.0f;
    for (int s = tid; s < NSPK; s += 256) sum += expf(row[s] - mx);
    red[tid] = sum; __syncthreads();
    for (int o = 128; o > 0; o >>= 1) {
        if (tid < o) red[tid] += red[tid + o];
        __syncthreads();
    }
    float lse = mx + logf(red[0]);

    for (int s = tid; s < NSPK; s += 256) out[(size_t)t * NSPK + s] = row[s] - lse;
}

// ---------------------------------------------------------------------------
extern "C" void kernel_launch(void* const* d_in, const int* in_sizes, int n_in,
                              void* d_out, int out_size) {
    const float* x     = (const float*)d_in[0];
    const float* w_ih0 = (const float*)d_in[1];
    const float* w_hh0 = (const float*)d_in[2];
    const float* b_ih0 = (const float*)d_in[3];
    const float* b_hh0 = (const float*)d_in[4];
    const float* w_ih1 = (const float*)d_in[5];
    const float* w_hh1 = (const float*)d_in[6];
    const float* b_ih1 = (const float*)d_in[7];
    const float* b_hh1 = (const float*)d_in[8];
    const float* w_ih2 = (const float*)d_in[9];
    const float* w_hh2 = (const float*)d_in[10];
    const float* b_ih2 = (const float*)d_in[11];
    const float* b_hh2 = (const float*)d_in[12];
    const float* w_lin = (const float*)d_in[13];
    const float* b_lin = (const float*)d_in[14];
    float* out = (float*)d_out;

    const int init_total = 3 * (TT + 1) * HID;
    init_kernel<<<(init_total + 255) / 256, 256>>>();
    xg0_kernel<<<TT / 8, 256>>>(x, w_ih0, b_ih0, b_hh0);

    // Prefer 16-CTA-cluster DSMEM pipeline; fall back to global-L2 version.
    cudaFuncSetAttribute(lstm_cluster,
                         cudaFuncAttributeNonPortableClusterSizeAllowed, 1);
    cudaLaunchConfig_t cfg = {};
    cfg.gridDim  = dim3(3 * GC, 1, 1);
    cfg.blockDim = dim3(THR_CL, 1, 1);
    cfg.dynamicSmemBytes = 0;
    cudaLaunchAttribute at[1];
    at[0].id = cudaLaunchAttributeClusterDimension;
    at[0].val.clusterDim.x = GC;
    at[0].val.clusterDim.y = 1;
    at[0].val.clusterDim.z = 1;
    cfg.attrs = at;
    cfg.numAttrs = 1;

    int maxc = 0;
    cudaError_t qe = cudaOccupancyMaxPotentialClusterSize(&maxc, lstm_cluster, &cfg);

    bool launched = false;
    if (qe == cudaSuccess && maxc >= GC) {
        cudaError_t le = cudaLaunchKernelEx(&cfg, lstm_cluster, w_hh0,
                                            w_ih1, w_hh1, b_ih1, b_hh1,
                                            w_ih2, w_hh2, b_ih2, b_hh2);
        launched = (le == cudaSuccess);
        if (!launched) (void)cudaGetLastError();   // clear sticky error
    }
    if (!launched) {
        lstm_pipeline<<<NCTA, 256>>>(w_hh0,
                                     w_ih1, w_hh1, b_ih1, b_hh1,
                                     w_ih2, w_hh2, b_ih2, b_hh2);
    }

    classify_kernel<<<dim3(TT / 8, 3), 512>>>(w_lin, b_lin);
    softmax_kernel<<<TT, 256>>>(out);
}

// round 16
// speedup vs baseline: 1.5947x; 1.0247x over previous
#include <cuda_runtime.h>
#include <cuda_bf16.h>
#include <math.h>
#include <stdint.h>

// Problem dims
#define TT    1024
#define HID   256
#define FIN   40
#define NSPK  1251
#define BATCH 64

// Global-fallback pipeline config
#define G      32
#define CHUNK  8
#define ROWS   32
#define NCTA   (3 * G)

// Cluster pipeline config
#define GC     16       // CTAs per layer-cluster
#define RR     64       // gate rows per CTA
#define CH     16       // h-indices per CTA
#define CW     64       // columns per dot warp
#define NW     8        // dot warps (warp 8 = reducer)
#define THR_CL 288
#define NCLS   80       // classifier CTAs (blocks 48..127)
#define NGRP   (TT / 8) // 128 timestep-groups

#define CANARY_I 0x7fb0beef

__device__ float g_hbuf[3][TT + 1][HID];
__device__ float g_xg0[TT][32][32];
__device__ float g_logits[TT * NSPK];

#define FMA2(d, a, b, c) \
    asm("fma.rn.f32x2 %0, %1, %2, %3;" : "=l"(d) : "l"(a), "l"(b), "l"(c))

__device__ __forceinline__ float tanh_fast(float x) {
    float r;
    asm("tanh.approx.f32 %0, %1;" : "=f"(r) : "f"(x));
    return r;
}
__device__ __forceinline__ float sig_fast(float x) {
    return 0.5f * tanh_fast(0.5f * x) + 0.5f;
}
__device__ __forceinline__ float poll_ld(const float* p) {
    float v;
    asm volatile("ld.volatile.global.f32 %0, [%1];" : "=f"(v) : "l"(p) : "memory");
    return v;
}
__device__ __forceinline__ void st_vol(float* p, float v) {
    asm volatile("st.volatile.global.f32 [%0], %1;" :: "l"(p), "f"(v) : "memory");
}
__device__ __forceinline__ void sts_f32(uint32_t a, float v) {
    asm volatile("st.shared.f32 [%0], %1;" :: "r"(a), "f"(v) : "memory");
}
__device__ __forceinline__ void sts_cluster(uint32_t a, float v) {
    asm volatile("st.shared::cluster.f32 [%0], %1;" :: "r"(a), "f"(v) : "memory");
}
__device__ __forceinline__ uint32_t mapa_u32(uint32_t a, uint32_t r) {
    uint32_t d;
    asm("mapa.shared::cluster.u32 %0, %1, %2;" : "=r"(d) : "r"(a), "r"(r));
    return d;
}
__device__ __forceinline__ void mbar_init(uint32_t a, uint32_t count) {
    asm volatile("mbarrier.init.shared.b64 [%0], %1;" :: "r"(a), "r"(count) : "memory");
}
__device__ __forceinline__ void mbar_arrive_remote(uint32_t a) {
    asm volatile("mbarrier.arrive.shared::cluster.b64 _, [%0];" :: "r"(a) : "memory");
}
// Sleeping parity wait, cluster-scope acquire (remote release-arrives).
#define MBAR_WAIT_CL(addr, par_) do { \
    uint32_t _done; \
    do { \
        asm volatile("{\n\t.reg .pred p;\n\t" \
            "mbarrier.try_wait.parity.acquire.cluster.shared::cta.b64 p, [%1], %2, 0x989680;\n\t" \
            "selp.b32 %0, 1, 0, p;\n\t}" \
            : "=r"(_done) : "r"((uint32_t)(addr)), "r"((uint32_t)(par_)) : "memory"); \
    } while (!_done); \
} while (0)

__device__ __forceinline__ unsigned long long pack2(float a, float b) {
    return (unsigned long long)__float_as_uint(a) |
           ((unsigned long long)__float_as_uint(b) << 32);
}
__device__ __forceinline__ float lo2(unsigned long long v) {
    return __uint_as_float((unsigned)(v & 0xffffffffull));
}
__device__ __forceinline__ float hi2(unsigned long long v) {
    return __uint_as_float((unsigned)(v >> 32));
}
#define CLUSTER_BAR() do { \
    asm volatile("barrier.cluster.arrive.aligned;" ::: "memory"); \
    asm volatile("barrier.cluster.wait.aligned;" ::: "memory"); \
} while (0)

// ---------------------------------------------------------------------------
// K1: init global h buffers: t==0 -> 0.0f, else canary
// ---------------------------------------------------------------------------
__global__ void init_kernel() {
    int idx = blockIdx.x * 256 + threadIdx.x;
    const int total = 3 * (TT + 1) * HID;
    if (idx < total) {
        int t = (idx / HID) % (TT + 1);
        ((float*)g_hbuf)[idx] = (t == 0) ? 0.0f : __int_as_float(CANARY_I);
    }
}

// ---------------------------------------------------------------------------
// K2: layer-0 input projection (+ both biases), permuted
// ---------------------------------------------------------------------------
__global__ void xg0_kernel(const float* __restrict__ x,
                           const float* __restrict__ w_ih0,
                           const float* __restrict__ b_ih0,
                           const float* __restrict__ b_hh0) {
    __shared__ float xs[8][FIN];
    const int t0 = blockIdx.x * 8;
    const int tid = threadIdx.x;

    for (int i = tid; i < 8 * FIN; i += 256) {
        int tt = i / FIN, f = i % FIN;
        xs[tt][f] = x[((size_t)(BATCH - 1) * TT + (t0 + tt)) * FIN + f];
    }
    __syncthreads();

    const int cta = tid >> 3;
    const int jj  = tid & 7;

    for (int q = 0; q < 4; q++) {
        int grow = q * 256 + tid;
        float w[FIN];
        const float4* wr = (const float4*)(w_ih0 + (size_t)grow * FIN);
        #pragma unroll
        for (int i = 0; i < FIN / 4; i++) {
            float4 v = wr[i];
            w[4 * i] = v.x; w[4 * i + 1] = v.y; w[4 * i + 2] = v.z; w[4 * i + 3] = v.w;
        }
        float bb = b_ih0[grow] + b_hh0[grow];
        #pragma unroll
        for (int tt = 0; tt < 8; tt++) {
            float s = bb;
            #pragma unroll
            for (int f = 0; f < FIN; f++) s += w[f] * xs[tt][f];
            g_xg0[t0 + tt][cta][q * 8 + jj] = s;
        }
    }
}

// ---------------------------------------------------------------------------
// Shared-memory overlay: pipeline arrays vs classifier arrays (never both)
// ---------------------------------------------------------------------------
struct PipeShm {
    float self_h[2][256];
    float in_stage[256];
    float psum[2][RR][NW];
    unsigned long long mbar_h;
};
struct ClsShm {
    float hs[8][HID];        // 8KB; reused as reduction scratch after logits
    float lg[8][NSPK];       // 40KB
};
union Shm {
    PipeShm p;
    ClsShm  c;
};

// ---------------------------------------------------------------------------
// K3a: CLUSTER pipeline (R13 winner, byte-identical recurrence) + FUSED
// classifier/softmax CTAs (blocks 48..127) that trail the pipeline.
// ---------------------------------------------------------------------------
__global__ void __launch_bounds__(THR_CL, 1)
lstm_cluster(const float* __restrict__ w_hh0,
             const float* __restrict__ w_ih1, const float* __restrict__ w_hh1,
             const float* __restrict__ b_ih1, const float* __restrict__ b_hh1,
             const float* __restrict__ w_ih2, const float* __restrict__ w_hh2,
             const float* __restrict__ b_ih2, const float* __restrict__ b_hh2,
             const float* __restrict__ wlin, const float* __restrict__ blin,
             float* __restrict__ out) {
    __shared__ __align__(16) Shm shm;

    const int bid  = blockIdx.x;
    const int tid  = threadIdx.x;

    // ======================= CLASSIFIER CTAs =======================
    if (bid >= 48) {
        // whole 16-CTA clusters take this branch (48 % 16 == 0): no cluster
        // barrier divergence. These CTAs never touch DSMEM.
        for (int g = bid - 48; g < NGRP; g += NCLS) {
            const int t0 = g * 8;
            // coarse sleep-wait: 1 thread, minimal L2 pressure on the pipeline
            if (tid == 0) {
                while (__float_as_int(poll_ld(&g_hbuf[2][t0 + 8][HID - 1])) == CANARY_I)
                    __nanosleep(256);
            }
            __syncthreads();
            // per-element canary load (handles per-producer-CTA stragglers)
            for (int i = tid; i < 8 * HID; i += THR_CL) {
                int tt = i >> 8, k = i & 255;
                const float* p = &g_hbuf[2][t0 + tt + 1][k];
                float v;
                do { v = poll_ld(p); } while (__float_as_int(v) == CANARY_I);
                shm.c.hs[tt][k] = v;
            }
            __syncthreads();

            // logits: 1251 speakers x 8 timesteps
            for (int spk = tid; spk < NSPK; spk += THR_CL) {
                const unsigned long long* wr =
                    (const unsigned long long*)(wlin + (size_t)spk * HID);
                unsigned long long acc[8];
                #pragma unroll
                for (int tt = 0; tt < 8; tt++) acc[tt] = 0ull;
                #pragma unroll 8
                for (int p = 0; p < HID / 2; p += 2) {
                    ulonglong2 wv = *(const ulonglong2*)&wr[p];
                    #pragma unroll
                    for (int tt = 0; tt < 8; tt++) {
                        ulonglong2 hv = *(const ulonglong2*)&shm.c.hs[tt][2 * p];
                        FMA2(acc[tt], wv.x, hv.x, acc[tt]);
                        FMA2(acc[tt], wv.y, hv.y, acc[tt]);
                    }
                }
                float bb = blin[spk];
                #pragma unroll
                for (int tt = 0; tt < 8; tt++)
                    shm.c.lg[tt][spk] = lo2(acc[tt]) + hi2(acc[tt]) + bb;
            }
            __syncthreads();

            // softmax per timestep; hs region reused as reduction scratch
            float* red = &shm.c.hs[0][0];
            for (int tt = 0; tt < 8; tt++) {
                const float* row = shm.c.lg[tt];
                float mx = -INFINITY;
                for (int s = tid; s < NSPK; s += THR_CL) mx = fmaxf(mx, row[s]);
                red[tid] = mx;
                __syncthreads();
                if (tid < 32) {
                    float m = red[tid];
                    for (int k = tid + 32; k < THR_CL; k += 32) m = fmaxf(m, red[k]);
                    #pragma unroll
                    for (int o = 16; o > 0; o >>= 1)
                        m = fmaxf(m, __shfl_xor_sync(0xffffffffu, m, o));
                    red[0] = m;
                }
                __syncthreads();
                mx = red[0];
                __syncthreads();

                float sum = 0.0f;
                for (int s = tid; s < NSPK; s += THR_CL) sum += expf(row[s] - mx);
                red[tid] = sum;
                __syncthreads();
                if (tid < 32) {
                    float m = red[tid];
                    for (int k = tid + 32; k < THR_CL; k += 32) m += red[k];
                    #pragma unroll
                    for (int o = 16; o > 0; o >>= 1)
                        m += __shfl_xor_sync(0xffffffffu, m, o);
                    red[0] = m;
                }
                __syncthreads();
                float lse = mx + logf(red[0]);
                __syncthreads();

                float* orow = out + (size_t)(t0 + tt) * NSPK;
                for (int s = tid; s < NSPK; s += THR_CL) orow[s] = row[s] - lse;
                __syncthreads();
            }
        }
        return;
    }

    // ======================= PIPELINE CTAs (R13 winner) =======================
    const int layer = bid >> 4;
    const int cta   = bid & 15;
    const int warp  = tid >> 5;
    const int lane  = tid & 31;

    const uint32_t mb_local = (uint32_t)__cvta_generic_to_shared(&shm.p.mbar_h);

    for (int i = tid; i < 256; i += THR_CL) {
        shm.p.self_h[0][i] = 0.0f;
        shm.p.self_h[1][i] = 0.0f;
    }
    if (tid == 0) mbar_init(mb_local, 16);
    __syncthreads();
    CLUSTER_BAR();   // all CTAs' mbarriers initialized before any remote arrive

    const float *wih = nullptr, *whh = nullptr, *bih = nullptr, *bhh = nullptr;
    if (layer == 0)      { whh = w_hh0; }
    else if (layer == 1) { wih = w_ih1; whh = w_hh1; bih = b_ih1; bhh = b_hh1; }
    else                 { wih = w_ih2; whh = w_hh2; bih = b_ih2; bhh = b_hh2; }

    if (warp < NW) {
        // ---------------- dot warps ----------------
        const bool self_side = (warp >= 4);
        const bool active = !(layer == 0 && !self_side);

        const int cs = self_side ? (warp - 4) * CW : warp * CW;
        const float* Wsrc = self_side ? whh : wih;

        unsigned long long w2[64];
        if (active) {
            #pragma unroll
            for (int k = 0; k < 2; k++) {
                int grow = ((lane >> 4) + 2 * k) * 256 + cta * CH + (lane & 15);
                const float* wr = Wsrc + (size_t)grow * HID + cs;
                #pragma unroll
                for (int j = 0; j < 32; j++)
                    w2[32 * k + j] = pack2(wr[2 * j], wr[2 * j + 1]);
            }
        }

        uint32_t pso[2];
        #pragma unroll
        for (int p = 0; p < 2; p++)
            pso[p] = (uint32_t)__cvta_generic_to_shared(&shm.p.psum[p][lane][warp]);

        for (int t = 0; t < TT; t++) {
            const int par = t & 1;
            if (active) {
                const float* hb;
                if (self_side) {
                    if (t > 0)
                        MBAR_WAIT_CL(mb_local, (uint32_t)((t - 1) & 1));  // sleep
                    hb = &shm.p.self_h[par][cs];
                } else {
                    const float* p0 = &g_hbuf[layer - 1][t + 1][cs + lane];
                    const float* p1 = p0 + 32;
                    float v0, v1; int got = 0;
                    do {
                        if (!(got & 1)) { v0 = poll_ld(p0); if (__float_as_int(v0) != CANARY_I) got |= 1; }
                        if (!(got & 2)) { v1 = poll_ld(p1); if (__float_as_int(v1) != CANARY_I) got |= 2; }
                    } while (got != 3);
                    shm.p.in_stage[cs + lane] = v0;
                    shm.p.in_stage[cs + lane + 32] = v1;
                    __syncwarp();
                    hb = &shm.p.in_stage[cs];
                }

                unsigned long long a00 = 0, a01 = 0, a10 = 0, a11 = 0;
                #pragma unroll
                for (int jj = 0; jj < 16; jj++) {
                    ulonglong2 hv = *(const ulonglong2*)(hb + 4 * jj);
                    FMA2(a00, w2[2 * jj],      hv.x, a00);
                    FMA2(a01, w2[2 * jj + 1],  hv.y, a01);
                    FMA2(a10, w2[32 + 2 * jj], hv.x, a10);
                    FMA2(a11, w2[33 + 2 * jj], hv.y, a11);
                }
                float pa = (lo2(a00) + hi2(a00)) + (lo2(a01) + hi2(a01));
                float pb = (lo2(a10) + hi2(a10)) + (lo2(a11) + hi2(a11));
                sts_f32(pso[par], pa);
                sts_f32(pso[par] + 32 * NW * 4, pb);
            }
            __syncthreads();   // B(t): psum(t) visible; reducer consumed psum(t-1)
        }
        CLUSTER_BAR();
        return;
    }

    // ---------------- reducer warp (warp 8) ----------------
    {
        int grow0 = (lane >> 4) * 256 + cta * CH + (lane & 15);
        int grow1 = grow0 + 2 * 256;
        float b0 = 0.0f, b1 = 0.0f;
        int xi0 = 0, xi1 = 0;
        if (layer > 0) {
            b0 = bih[grow0] + bhh[grow0];
            b1 = bih[grow1] + bhh[grow1];
        } else {
            int r0 = grow0 & 255, r1 = grow1 & 255;
            xi0 = ((r0 >> 3) << 5) + ((grow0 >> 8) << 3) + (r0 & 7);
            xi1 = ((r1 >> 3) << 5) + ((grow1 >> 8) << 3) + (r1 & 7);
        }

        const int j = lane & 15;
        const int pbase = (lane >> 4) * 8;

        uint32_t hrem[2][8];
        #pragma unroll
        for (int p = 0; p < 2; p++) {
            uint32_t la = (uint32_t)__cvta_generic_to_shared(&shm.p.self_h[p][cta * CH + j]);
            #pragma unroll
            for (int i = 0; i < 8; i++)
                hrem[p][i] = mapa_u32(la, pbase + i);
        }
        uint32_t mb_rem = (lane < 16) ? mapa_u32(mb_local, lane) : 0;

        float creg = 0.0f;

        for (int t = 0; t < TT; t++) {
            const int par = t & 1;
            float xga = 0.0f, xgb = 0.0f;
            if (layer == 0) {
                const float* xf = (const float*)g_xg0 + (size_t)t * 1024;
                xga = __ldg(xf + xi0);
                xgb = __ldg(xf + xi1);
            }

            __syncthreads();   // B(t): dot warps' psum(t) now visible

            float rs0, rs1;
            if (layer == 0) {
                float4 A1 = *(const float4*)&shm.p.psum[par][lane][4];
                float4 B1 = *(const float4*)&shm.p.psum[par][lane + 32][4];
                rs0 = (A1.x + A1.y) + (A1.z + A1.w) + xga;
                rs1 = (B1.x + B1.y) + (B1.z + B1.w) + xgb;
            } else {
                float4 A0 = *(const float4*)&shm.p.psum[par][lane][0];
                float4 A1 = *(const float4*)&shm.p.psum[par][lane][4];
                float4 B0 = *(const float4*)&shm.p.psum[par][lane + 32][0];
                float4 B1 = *(const float4*)&shm.p.psum[par][lane + 32][4];
                rs0 = ((A0.x + A0.y) + (A0.z + A0.w)) + ((A1.x + A1.y) + (A1.z + A1.w)) + b0;
                rs1 = ((B0.x + B0.y) + (B0.z + B0.w)) + ((B1.x + B1.y) + (B1.z + B1.w)) + b1;
            }

            float vi = __shfl_sync(0xffffffffu, rs0, j);
            float vf = __shfl_sync(0xffffffffu, rs0, j + 16);
            float vg = __shfl_sync(0xffffffffu, rs1, j);
            float vo = __shfl_sync(0xffffffffu, rs1, j + 16);

            float i_ = sig_fast(vi);
            float f_ = sig_fast(vf);
            float g_ = tanh_fast(vg);
            float o_ = sig_fast(vo);
            creg = f_ * creg + i_ * g_;
            float h = o_ * tanh_fast(creg);

            const uint32_t* hr = hrem[par ^ 1];
            #pragma unroll
            for (int i = 0; i < 8; i++)
                sts_cluster(hr[i], h);
            if (lane < 16)
                st_vol(&g_hbuf[layer][t + 1][cta * CH + j], h);
            __syncwarp();
            if (lane < 16)
                mbar_arrive_remote(mb_rem);
        }
        CLUSTER_BAR();
    }
}

// ---------------------------------------------------------------------------
// K3b: FALLBACK global-L2 pipeline (proven R2 kernel)
// ---------------------------------------------------------------------------
__global__ void __launch_bounds__(256, 1)
lstm_pipeline(const float* __restrict__ w_hh0,
              const float* __restrict__ w_ih1, const float* __restrict__ w_hh1,
              const float* __restrict__ b_ih1, const float* __restrict__ b_hh1,
              const float* __restrict__ w_ih2, const float* __restrict__ w_hh2,
              const float* __restrict__ b_ih2, const float* __restrict__ b_hh2) {
    __shared__ float harr[512];
    __shared__ float psum[2][8][32];

    const int layer = blockIdx.x >> 5;
    const int cta   = blockIdx.x & 31;
    const int warp  = threadIdx.x >> 5;
    const int lane  = threadIdx.x & 31;

    const float *wih = nullptr, *whh = nullptr, *bih = nullptr, *bhh = nullptr;
    if (layer == 0)      { whh = w_hh0; }
    else if (layer == 1) { wih = w_ih1; whh = w_hh1; bih = b_ih1; bhh = b_hh1; }
    else                 { wih = w_ih2; whh = w_hh2; bih = b_ih2; bhh = b_hh2; }

    const int grow = (lane >> 3) * HID + cta * CHUNK + (lane & 7);

    unsigned long long w2[32];
    if (layer == 0) {
        const int C = warp * 32;
        #pragma unroll
        for (int j = 0; j < 16; j++)
            w2[j] = pack2(whh[(size_t)grow * HID + C + 2 * j],
                          whh[(size_t)grow * HID + C + 2 * j + 1]);
    } else {
        const int C = warp * 64;
        #pragma unroll
        for (int j = 0; j < 32; j++) {
            int c = C + 2 * j;
            float a, b;
            if (c < HID) { a = wih[(size_t)grow * HID + c];
                           b = wih[(size_t)grow * HID + c + 1]; }
            else         { a = whh[(size_t)grow * HID + c - HID];
                           b = whh[(size_t)grow * HID + c - HID + 1]; }
            w2[j] = pack2(a, b);
        }
    }

    float biasr = 0.0f;
    if (warp == 7 && layer > 0) biasr = bih[grow] + bhh[grow];

    float creg = 0.0f;
    int par = 0;

    for (int t = 0; t < TT; t++) {
        float xgv = 0.0f;
        if (layer == 0 && warp == 7) xgv = g_xg0[t][cta][lane];

        if (layer == 0) {
            const float* p = &g_hbuf[0][t][warp * 32 + lane];
            float v;
            do { v = poll_ld(p); } while (__float_as_int(v) == CANARY_I);
            harr[warp * 32 + lane] = v;
        } else if (warp < 4) {
            const float* p0 = &g_hbuf[layer - 1][t + 1][warp * 64 + lane];
            const float* p1 = p0 + 32;
            float v0, v1; int got = 0;
            do {
                if (!(got & 1)) { v0 = poll_ld(p0); if (__float_as_int(v0) != CANARY_I) got |= 1; }
                if (!(got & 2)) { v1 = poll_ld(p1); if (__float_as_int(v1) != CANARY_I) got |= 2; }
            } while (got != 3);
            harr[warp * 64 + lane] = v0;
            harr[warp * 64 + 32 + lane] = v1;
        } else {
            const float* p0 = &g_hbuf[layer][t][(warp - 4) * 64 + lane];
            const float* p1 = p0 + 32;
            float v0, v1; int got = 0;
            do {
                if (!(got & 1)) { v0 = poll_ld(p0); if (__float_as_int(v0) != CANARY_I) got |= 1; }
                if (!(got & 2)) { v1 = poll_ld(p1); if (__float_as_int(v1) != CANARY_I) got |= 2; }
            } while (got != 3);
            harr[warp * 64 + lane] = v0;
            harr[warp * 64 + 32 + lane] = v1;
        }
        __syncwarp(0xffffffffu);

        unsigned long long acc0 = 0ull, acc1 = 0ull;
        if (layer == 0) {
            const float* hb = &harr[warp * 32];
            #pragma unroll
            for (int i = 0; i < 8; i++) {
                ulonglong2 hv = *(const ulonglong2*)&hb[4 * i];
                FMA2(acc0, w2[2 * i],     hv.x, acc0);
                FMA2(acc1, w2[2 * i + 1], hv.y, acc1);
            }
        } else {
            const float* hb = &harr[warp * 64];
            #pragma unroll
            for (int i = 0; i < 16; i++) {
                ulonglong2 hv = *(const ulonglong2*)&hb[4 * i];
                FMA2(acc0, w2[2 * i],     hv.x, acc0);
                FMA2(acc1, w2[2 * i + 1], hv.y, acc1);
            }
        }
        float partial = (lo2(acc0) + hi2(acc0)) + (lo2(acc1) + hi2(acc1));
        psum[par][warp][lane] = partial;

        __syncthreads();

        if (warp == 7) {
            float rs = psum[par][0][lane] + psum[par][1][lane]
                     + psum[par][2][lane] + psum[par][3][lane]
                     + psum[par][4][lane] + psum[par][5][lane]
                     + psum[par][6][lane] + psum[par][7][lane];
            rs += (layer == 0) ? xgv : biasr;

            int j = lane & 7;
            float vi = __shfl_sync(0xffffffffu, rs, j);
            float vf = __shfl_sync(0xffffffffu, rs, j + 8);
            float vg = __shfl_sync(0xffffffffu, rs, j + 16);
            float vo = __shfl_sync(0xffffffffu, rs, j + 24);

            float i_ = sig_fast(vi);
            float f_ = sig_fast(vf);
            float g_ = tanh_fast(vg);
            float o_ = sig_fast(vo);
            creg = f_ * creg + i_ * g_;
            float h = o_ * tanh_fast(creg);
            if (lane < CHUNK)
                st_vol(&g_hbuf[layer][t + 1][cta * CHUNK + lane], h);
        }
        par ^= 1;
    }
}

// ---------------------------------------------------------------------------
// K4: classifier GEMM (fallback path only)
// ---------------------------------------------------------------------------
__global__ void __launch_bounds__(512)
classify_kernel(const float* __restrict__ wlin,
                const float* __restrict__ blin) {
    __shared__ float hs[8][HID];
    const int t0 = blockIdx.x * 8;
    const int tid = threadIdx.x;

    for (int i = tid; i < 8 * HID; i += 512) {
        int tt = i >> 8, k = i & 255;
        hs[tt][k] = g_hbuf[2][t0 + tt + 1][k];
    }
    __syncthreads();

    int spk = blockIdx.y * 512 + tid;
    if (spk < NSPK) {
        const unsigned long long* wr =
            (const unsigned long long*)(wlin + (size_t)spk * HID);
        unsigned long long acc[8];
        #pragma unroll
        for (int tt = 0; tt < 8; tt++) acc[tt] = 0ull;

        #pragma unroll 8
        for (int p = 0; p < HID / 2; p += 2) {
            ulonglong2 wv = *(const ulonglong2*)&wr[p];
            #pragma unroll
            for (int tt = 0; tt < 8; tt++) {
                ulonglong2 hv = *(const ulonglong2*)&hs[tt][2 * p];
                FMA2(acc[tt], wv.x, hv.x, acc[tt]);
                FMA2(acc[tt], wv.y, hv.y, acc[tt]);
            }
        }
        float bb = blin[spk];
        #pragma unroll
        for (int tt = 0; tt < 8; tt++) {
            g_logits[(size_t)(t0 + tt) * NSPK + spk] =
                lo2(acc[tt]) + hi2(acc[tt]) + bb;
        }
    }
}

// ---------------------------------------------------------------------------
// K5: row-wise log_softmax (fallback path only)
// ---------------------------------------------------------------------------
__global__ void softmax_kernel(float* __restrict__ out) {
    const int t = blockIdx.x;
    const int tid = threadIdx.x;
    __shared__ float red[256];
    const float* row = g_logits + (size_t)t * NSPK;

    float mx = -INFINITY;
    for (int s = tid; s < NSPK; s += 256) mx = fmaxf(mx, row[s]);
    red[tid] = mx; __syncthreads();
    for (int o = 128; o > 0; o >>= 1) {
        if (tid < o) red[tid] = fmaxf(red[tid], red[tid + o]);
        __syncthreads();
    }
    mx = red[0]; __syncthreads();

    float sum = 0.0f;
    for (int s = tid; s < NSPK; s += 256) sum += expf(row[s] - mx);
    red[tid] = sum; __syncthreads();
    for (int o = 128; o > 0; o >>= 1) {
        if (tid < o) red[tid] += red[tid + o];
        __syncthreads();
    }
    float lse = mx + logf(red[0]);

    for (int s = tid; s < NSPK; s += 256) out[(size_t)t * NSPK + s] = row[s] - lse;
}

// ---------------------------------------------------------------------------
extern "C" void kernel_launch(void* const* d_in, const int* in_sizes, int n_in,
                              void* d_out, int out_size) {
    const float* x     = (const float*)d_in[0];
    const float* w_ih0 = (const float*)d_in[1];
    const float* w_hh0 = (const float*)d_in[2];
    const float* b_ih0 = (const float*)d_in[3];
    const float* b_hh0 = (const float*)d_in[4];
    const float* w_ih1 = (const float*)d_in[5];
    const float* w_hh1 = (const float*)d_in[6];
    const float* b_ih1 = (const float*)d_in[7];
    const float* b_hh1 = (const float*)d_in[8];
    const float* w_ih2 = (const float*)d_in[9];
    const float* w_hh2 = (const float*)d_in[10];
    const float* b_ih2 = (const float*)d_in[11];
    const float* b_hh2 = (const float*)d_in[12];
    const float* w_lin = (const float*)d_in[13];
    const float* b_lin = (const float*)d_in[14];
    float* out = (float*)d_out;

    const int init_total = 3 * (TT + 1) * HID;
    init_kernel<<<(init_total + 255) / 256, 256>>>();
    xg0_kernel<<<TT / 8, 256>>>(x, w_ih0, b_ih0, b_hh0);

    // Fused pipeline+classifier: 128 CTAs = 8 clusters of 16 (all co-resident).
    cudaFuncSetAttribute(lstm_cluster,
                         cudaFuncAttributeNonPortableClusterSizeAllowed, 1);
    cudaLaunchConfig_t cfg = {};
    cfg.gridDim  = dim3(48 + NCLS, 1, 1);
    cfg.blockDim = dim3(THR_CL, 1, 1);
    cfg.dynamicSmemBytes = 0;
    cudaLaunchAttribute at[1];
    at[0].id = cudaLaunchAttributeClusterDimension;
    at[0].val.clusterDim.x = GC;
    at[0].val.clusterDim.y = 1;
    at[0].val.clusterDim.z = 1;
    cfg.attrs = at;
    cfg.numAttrs = 1;

    int maxc = 0;
    cudaError_t qe = cudaOccupancyMaxPotentialClusterSize(&maxc, lstm_cluster, &cfg);

    bool launched = false;
    if (qe == cudaSuccess && maxc >= GC) {
        cudaError_t le = cudaLaunchKernelEx(&cfg, lstm_cluster, w_hh0,
                                            w_ih1, w_hh1, b_ih1, b_hh1,
                                            w_ih2, w_hh2, b_ih2, b_hh2,
                                            w_lin, b_lin, out);
        launched = (le == cudaSuccess);
        if (!launched) (void)cudaGetLastError();   // clear sticky error
    }
    if (!launched) {
        lstm_pipeline<<<NCTA, 256>>>(w_hh0,
                                     w_ih1, w_hh1, b_ih1, b_hh1,
                                     w_ih2, w_hh2, b_ih2, b_hh2);
        classify_kernel<<<dim3(TT / 8, 3), 512>>>(w_lin, b_lin);
        softmax_kernel<<<TT, 256>>>(out);
    }
}